// round 14
// baseline (speedup 1.0000x reference)
#include <cuda_runtime.h>
#include <math.h>

#define BB 2
#define NA 2048
#define NATOMS (BB*NA)
#define BOXF 27.0f
#define SEL0 46
#define SEL1 92
#define ASEL0 16
#define ASEL1 32
#define NANG (ASEL0+ASEL1)      /* 48  */
#define NRAD (SEL0+SEL1)        /* 138 */
#define DDIM (NRAD + 3*NANG)    /* 282 */
#define HID 64
#define EPSF 1e-16f
#define FULLM 0xFFFFFFFFu

#define WPB 8
#define BWPB 16               /* atoms per block in bwd (512 threads) */
#define NBINW 128
#define BSCALEW 9.375f
#define CAPW0 96
#define CAPW1 160

__device__ float g_dist0[NATOMS*SEL0];
__device__ int   g_idx0 [NATOMS*SEL0];
__device__ float g_dist1[NATOMS*SEL1];
__device__ int   g_idx1 [NATOMS*SEL1];
__device__ float4 g_frame[NATOMS*3];
__device__ float g_desc [NATOMS*DDIM];
__device__ float g_gdesc[NATOMS*DDIM];
__device__ float g_grad [NATOMS*3];
__device__ float g_e    [NATOMS];
__device__ float g_W0T  [2*HID*DDIM];
__device__ float g_W1T  [2*HID*HID];
__device__ int   g_perm [NATOMS];
__device__ int   g_cnt  [2];

__device__ __forceinline__ float mic(float d){
    return d - BOXF * rintf(d * (1.0f/BOXF));
}
__device__ __forceinline__ float wred(float v){
    v += __shfl_xor_sync(FULLM, v, 16);
    v += __shfl_xor_sync(FULLM, v, 8);
    v += __shfl_xor_sync(FULLM, v, 4);
    v += __shfl_xor_sync(FULLM, v, 2);
    v += __shfl_xor_sync(FULLM, v, 1);
    return v;
}
__device__ __forceinline__ void wmin2(float &d, int &i){
    #pragma unroll
    for (int off = 16; off > 0; off >>= 1){
        float od = __shfl_xor_sync(FULLM, d, off);
        int   oi = __shfl_xor_sync(FULLM, i, off);
        if (od < d){ d = od; i = oi; }
    }
}

// ---------------------------------------------------------------------------
// Prep: weight transposes + grad zero + type-partition permutation (fused)
// ---------------------------------------------------------------------------
__global__ void prep_kernel(const int* __restrict__ types,
    const float* __restrict__ W00, const float* __restrict__ W10,
    const float* __restrict__ W01, const float* __restrict__ W11){
    __shared__ int wb[8][2];
    int tid = threadIdx.x;
    int idx = blockIdx.x*blockDim.x + tid;
    if (idx < 2*DDIM*HID){
        int t = idx / (DDIM*HID);
        int r = idx % (DDIM*HID);
        int d = r / HID, s = r % HID;
        const float* W = t ? W10 : W00;
        g_W0T[t*HID*DDIM + s*DDIM + d] = W[r];
    }
    if (idx < 2*HID*HID){
        int t = idx / (HID*HID);
        int r = idx % (HID*HID);
        int c = r / HID, s = r % HID;
        const float* W = t ? W11 : W01;
        g_W1T[t*HID*HID + s*HID + c] = W[r];
    }
    if (idx < NATOMS*3) g_grad[idx] = 0.0f;
    if (idx < NATOMS){
        int lane = tid & 31, w = tid >> 5;
        unsigned lanelt = (1u << lane) - 1u;
        int t = types[idx];
        unsigned m0 = __ballot_sync(FULLM, t == 0);
        int n0 = __popc(m0);
        if (lane == 0){
            wb[w][0] = atomicAdd(&g_cnt[0], n0);
            wb[w][1] = atomicAdd(&g_cnt[1], 32 - n0);
        }
        __syncwarp();
        int pos = (t == 0) ? (wb[w][0] + __popc(m0 & lanelt))
                           : (NATOMS - 1 - (wb[w][1] + __popc(~m0 & lanelt)));
        g_perm[pos] = idx;
    }
}

// ---------------------------------------------------------------------------
// K1: fused warp-per-atom kNN (histogram select) + descriptor fwd + frame out
// ---------------------------------------------------------------------------
__global__ void knnd_kernel(const float* __restrict__ xyz, const int* __restrict__ types){
    __shared__ float4 sp[NA];
    __shared__ unsigned int hist[WPB][NBINW];
    __shared__ unsigned long long c0buf[WPB][CAPW0];
    __shared__ unsigned long long c1buf[WPB][CAPW1];

    int tid = threadIdx.x;
    int w = tid >> 5, lane = tid & 31;
    int atom = blockIdx.x*WPB + w;
    int b = atom >> 11, i = atom & (NA-1);
    const float* xb = xyz + (size_t)b*NA*3;
    const int* tb = types + (size_t)b*NA;

    for (int j = tid; j < NA; j += WPB*32)
        sp[j] = make_float4(xb[3*j+0], xb[3*j+1], xb[3*j+2], __int_as_float(tb[j]));
    __syncthreads();

    float4 pi = sp[i];
    float xi = pi.x, yi = pi.y, zi = pi.z;

    #pragma unroll
    for (int q = 0; q < NBINW/32; q++) hist[w][lane + 32*q] = 0;
    __syncwarp();

    /* pass 1: packed histogram */
    for (int j = lane; j < NA; j += 32){
        if (j == i) continue;
        float4 p = sp[j];
        float dx = mic(xi - p.x + EPSF);
        float dy = mic(yi - p.y + EPSF);
        float dz = mic(zi - p.z + EPSF);
        float d = sqrtf(dx*dx + dy*dy + dz*dz);
        int bn = (int)(d * BSCALEW); if (bn > NBINW-1) bn = NBINW-1;
        atomicAdd(&hist[w][bn], __float_as_int(p.w) ? 0x10000u : 1u);
    }
    __syncwarp();

    /* threshold scan */
    unsigned chunk = 0;
    #pragma unroll
    for (int q = 0; q < 4; q++) chunk += hist[w][4*lane + q];
    unsigned incl = chunk;
    #pragma unroll
    for (int off = 1; off < 32; off <<= 1){
        unsigned v = __shfl_up_sync(FULLM, incl, off);
        if (lane >= off) incl += v;
    }
    unsigned excl = incl - chunk;

    int thr0, thr1;
    {
        unsigned m0 = __ballot_sync(FULLM, (incl & 0xFFFFu) >= SEL0);
        int fl = __ffs(m0) - 1;
        int tl = 0;
        if (lane == fl){
            int c = (int)(excl & 0xFFFFu);
            int bq = 4*lane;
            #pragma unroll
            for (int q = 0; q < 4; q++){
                c += (int)(hist[w][bq] & 0xFFFFu);
                if (c >= SEL0) break;
                bq++;
            }
            tl = bq;
        }
        thr0 = __shfl_sync(FULLM, tl, fl);
    }
    {
        unsigned m1 = __ballot_sync(FULLM, (incl >> 16) >= SEL1);
        int fl = __ffs(m1) - 1;
        int tl = 0;
        if (lane == fl){
            int c = (int)(excl >> 16);
            int bq = 4*lane;
            #pragma unroll
            for (int q = 0; q < 4; q++){
                c += (int)(hist[w][bq] >> 16);
                if (c >= SEL1) break;
                bq++;
            }
            tl = bq;
        }
        thr1 = __shfl_sync(FULLM, tl, fl);
    }

    /* pass 2: ballot compaction */
    unsigned lanelt = (1u << lane) - 1u;
    int cnt0 = 0, cnt1 = 0;
    for (int j = lane; j < NA; j += 32){
        float4 p = sp[j];
        int t = (j == i) ? 2 : __float_as_int(p.w);
        float dx = mic(xi - p.x + EPSF);
        float dy = mic(yi - p.y + EPSF);
        float dz = mic(zi - p.z + EPSF);
        float d = sqrtf(dx*dx + dy*dy + dz*dz);
        int bn = (int)(d * BSCALEW); if (bn > NBINW-1) bn = NBINW-1;
        unsigned long long key = ((unsigned long long)__float_as_uint(d) << 11)
                               | (unsigned long long)j;
        bool p0 = (t == 0) && (bn <= thr0);
        bool p1 = (t == 1) && (bn <= thr1);
        unsigned m0 = __ballot_sync(FULLM, p0);
        unsigned m1 = __ballot_sync(FULLM, p1);
        if (p0){ int pos = cnt0 + __popc(m0 & lanelt); if (pos < CAPW0) c0buf[w][pos] = key; }
        if (p1){ int pos = cnt1 + __popc(m1 & lanelt); if (pos < CAPW1) c1buf[w][pos] = key; }
        cnt0 += __popc(m0); cnt1 += __popc(m1);
    }
    if (cnt0 > CAPW0) cnt0 = CAPW0;
    if (cnt1 > CAPW1) cnt1 = CAPW1;
    __syncwarp();

    /* rank sort + write; capture top-2 per type via shuffle-argmin */
    float t0d0 = INFINITY, t0d1 = INFINITY; int t0i0 = 0, t0i1 = 0;
    float t1d0 = INFINITY, t1d1 = INFINITY; int t1i0 = 0, t1i1 = 0;

    for (int m = lane; m < cnt0; m += 32){
        unsigned long long k64 = c0buf[w][m];
        int r = 0;
        for (int q = 0; q < cnt0; q++) r += (c0buf[w][q] < k64);
        float dv = __uint_as_float((unsigned)(k64 >> 11));
        int jv = (int)(k64 & 2047ULL);
        if (r == 0){ t0d0 = dv; t0i0 = jv; }
        else if (r == 1){ t0d1 = dv; t0i1 = jv; }
        if (r < SEL0){
            g_dist0[(size_t)atom*SEL0 + r] = dv;
            g_idx0 [(size_t)atom*SEL0 + r] = jv;
        }
    }
    for (int m = lane; m < cnt1; m += 32){
        unsigned long long k64 = c1buf[w][m];
        int r = 0;
        for (int q = 0; q < cnt1; q++) r += (c1buf[w][q] < k64);
        float dv = __uint_as_float((unsigned)(k64 >> 11));
        int jv = (int)(k64 & 2047ULL);
        if (r == 0){ t1d0 = dv; t1i0 = jv; }
        else if (r == 1){ t1d1 = dv; t1i1 = jv; }
        if (r < SEL1){
            g_dist1[(size_t)atom*SEL1 + r] = dv;
            g_idx1 [(size_t)atom*SEL1 + r] = jv;
        }
    }
    __threadfence_block();
    __syncwarp();

    wmin2(t0d0, t0i0); wmin2(t0d1, t0i1);
    wmin2(t1d0, t1i0); wmin2(t1d1, t1i1);

    /* ---- local frame (uniform across warp) ---- */
    float d0, d1; int j0, j1;
    if (t1d0 < t0d0){ d0 = t1d0; j0 = t1i0; } else { d0 = t0d0; j0 = t0i0; }
    if (t1d1 < t0d1){ d1 = t1d1; j1 = t1i1; } else { d1 = t0d1; j1 = t0i1; }

    float4 pj0 = sp[j0], pj1 = sp[j1];
    float rv0x = mic(xi - pj0.x + EPSF);
    float rv0y = mic(yi - pj0.y + EPSF);
    float rv0z = mic(zi - pj0.z + EPSF);
    float rv1x = mic(xi - pj1.x + EPSF);
    float rv1y = mic(yi - pj1.y + EPSF);
    float rv1z = mic(zi - pj1.z + EPSF);

    float inv0 = 1.0f/(d0 + EPSF);
    float inv1 = 1.0f/(d1 + EPSF);
    float r0x = rv0x*inv0, r0y = rv0y*inv0, r0z = rv0z*inv0;
    float r1x = rv1x*inv1, r1y = rv1y*inv1, r1z = rv1z*inv1;

    float s = r0x*r1x + r0y*r1y + r0z*r1z;
    float px = r1x - s*r0x, py = r1y - s*r0y, pz = r1z - s*r0z;
    float np = sqrtf(px*px + py*py + pz*pz);
    float invnp = 1.0f/np;
    float v2x = px*invnp, v2y = py*invnp, v2z = pz*invnp;

    float cx = r0y*r1z - r0z*r1y;
    float cy = r0z*r1x - r0x*r1z;
    float cz = r0x*r1y - r0y*r1x;
    float nc = sqrtf(cx*cx + cy*cy + cz*cz);
    float invnc = 1.0f/nc;
    float v3x = cx*invnc, v3y = cy*invnc, v3z = cz*invnc;

    if (lane == 0){
        g_frame[(size_t)atom*3 + 0] = make_float4(rv0x, rv0y, rv0z, d0);
        g_frame[(size_t)atom*3 + 1] = make_float4(rv1x, rv1y, rv1z, d1);
        g_frame[(size_t)atom*3 + 2] = make_float4(np, nc,
                                     __int_as_float(j0), __int_as_float(j1));
    }

    /* ---- descriptor ---- */
    float* dsc = g_desc + (size_t)atom*DDIM;
    for (int m = lane; m < NRAD; m += 32){
        float sd = (m < SEL0) ? g_dist0[(size_t)atom*SEL0 + m]
                              : g_dist1[(size_t)atom*SEL1 + (m - SEL0)];
        dsc[m] = 1.0f/(sd + EPSF);
    }
    for (int k = lane; k < NANG; k += 32){
        int j; float d;
        if (k < ASEL0){ j = g_idx0[(size_t)atom*SEL0 + k]; d = g_dist0[(size_t)atom*SEL0 + k]; }
        else          { j = g_idx1[(size_t)atom*SEL1 + (k-ASEL0)]; d = g_dist1[(size_t)atom*SEL1 + (k-ASEL0)]; }
        float4 p = sp[j];
        float rx = mic(xi - p.x + EPSF);
        float ry = mic(yi - p.y + EPSF);
        float rz = mic(zi - p.z + EPSF);
        float inv = 1.0f/(d + EPSF);
        float ww = inv*inv;
        dsc[NRAD + 3*k + 0] = (r0x*rx + r0y*ry + r0z*rz)*ww;
        dsc[NRAD + 3*k + 1] = (v2x*rx + v2y*ry + v2z*rz)*ww;
        dsc[NRAD + 3*k + 2] = (v3x*rx + v3y*ry + v3z*rz)*ww;
    }
}

// ---------------------------------------------------------------------------
// K3: fused MLP fwd+bwd, K-split across two thread-halves (block = 512)
// ---------------------------------------------------------------------------
#define APB 8

__global__ void mlp_kernel(const int* __restrict__ types,
    const float* __restrict__ W00, const float* __restrict__ b00,
    const float* __restrict__ W01, const float* __restrict__ b01,
    const float* __restrict__ W02, const float* __restrict__ b02,
    const float* __restrict__ W10, const float* __restrict__ b10,
    const float* __restrict__ W11, const float* __restrict__ b11,
    const float* __restrict__ W12, const float* __restrict__ b12){

    __shared__ int   satom[APB];
    __shared__ float sX[APB][DDIM];
    __shared__ float ps[2][APB][HID];
    __shared__ float sH1[APB][HID];
    __shared__ float sG[APB][HID];
    __shared__ float sZ[APB][HID];
    __shared__ float red[APB][HID];

    int tid = threadIdx.x;               /* 0..511 */
    int j = tid & (HID-1);
    int g = (tid >> 6) & 3;
    int half = tid >> 8;                 /* 0 or 1 */
    int base = blockIdx.x * APB;

    if (tid < APB) satom[tid] = g_perm[base + tid];
    __syncthreads();

    for (int d = tid; d < APB*DDIM; d += 512){
        int aa = d / DDIM, dd = d % DDIM;
        sX[aa][dd] = g_desc[(size_t)satom[aa]*DDIM + dd];
    }
    __syncthreads();

    int a0 = 2*g, a1 = 2*g+1;
    int atom0 = satom[a0], atom1 = satom[a1];
    int t0 = types[atom0], t1 = types[atom1];
    const float* x0 = sX[a0];
    const float* x1 = sX[a1];

    /* ---- layer 1: K split [0,142) / [142,282) ---- */
    int dlo = half ? 142 : 0;
    int dhi = half ? DDIM : 142;
    float p0, p1;
    if (t0 == t1){
        const float* W = t0 ? W10 : W00;
        float e0 = 0.f, e1 = 0.f, o0 = 0.f, o1 = 0.f;
        #pragma unroll 4
        for (int d = dlo; d < dhi; d += 2){
            float w0 = W[d*HID + j];
            float w1 = W[(d+1)*HID + j];
            e0 = fmaf(x0[d],   w0, e0);
            e1 = fmaf(x1[d],   w0, e1);
            o0 = fmaf(x0[d+1], w1, o0);
            o1 = fmaf(x1[d+1], w1, o1);
        }
        p0 = e0 + o0; p1 = e1 + o1;
    } else {
        const float* Wa = t0 ? W10 : W00;
        const float* Wb = t1 ? W10 : W00;
        float e0 = 0.f, e1 = 0.f, o0 = 0.f, o1 = 0.f;
        #pragma unroll 2
        for (int d = dlo; d < dhi; d += 2){
            e0 = fmaf(x0[d],   Wa[d*HID + j],     e0);
            e1 = fmaf(x1[d],   Wb[d*HID + j],     e1);
            o0 = fmaf(x0[d+1], Wa[(d+1)*HID + j], o0);
            o1 = fmaf(x1[d+1], Wb[(d+1)*HID + j], o1);
        }
        p0 = e0 + o0; p1 = e1 + o1;
    }
    ps[half][a0][j] = p0;
    ps[half][a1][j] = p1;
    __syncthreads();

    float h1a = 0.f, h1b = 0.f;
    if (half == 0){
        h1a = tanhf(ps[0][a0][j] + ps[1][a0][j] + (t0 ? b10 : b00)[j]);
        h1b = tanhf(ps[0][a1][j] + ps[1][a1][j] + (t1 ? b10 : b00)[j]);
        sH1[a0][j] = h1a;
        sH1[a1][j] = h1b;
    }
    __syncthreads();

    /* ---- layer 2: K split 32/32 ---- */
    int slo = half*32;
    const float* h0 = sH1[a0];
    const float* h1r = sH1[a1];
    float q0 = 0.f, q1 = 0.f;
    if (t0 == t1){
        const float* W = t0 ? W11 : W01;
        #pragma unroll 8
        for (int q = 0; q < 32; q++){
            int ss = slo + q;
            float w = W[ss*HID + j];
            q0 = fmaf(h0[ss],  w, q0);
            q1 = fmaf(h1r[ss], w, q1);
        }
    } else {
        const float* Wa = t0 ? W11 : W01;
        const float* Wb = t1 ? W11 : W01;
        #pragma unroll 8
        for (int q = 0; q < 32; q++){
            int ss = slo + q;
            q0 = fmaf(h0[ss],  Wa[ss*HID + j], q0);
            q1 = fmaf(h1r[ss], Wb[ss*HID + j], q1);
        }
    }
    ps[half][a0][j] = q0;
    ps[half][a1][j] = q1;
    __syncthreads();

    if (half == 0){
        float h2a = tanhf(ps[0][a0][j] + ps[1][a0][j] + (t0 ? b11 : b01)[j]);
        float h2b = tanhf(ps[0][a1][j] + ps[1][a1][j] + (t1 ? b11 : b01)[j]);
        float w2a = (t0 ? W12 : W02)[j];
        float w2b = (t1 ? W12 : W02)[j];
        red[a0][j] = h2a * w2a;
        red[a1][j] = h2b * w2b;
        sG[a0][j] = w2a * (1.0f - h2a*h2a);
        sG[a1][j] = w2b * (1.0f - h2b*h2b);
    }
    __syncthreads();

    /* energy reduce on first 8 warps */
    if (half == 0){
        int ww = tid >> 5, lane = tid & 31;
        float v = red[ww][lane] + red[ww][lane+32];
        v = wred(v);
        if (lane == 0){
            int at = satom[ww];
            int tt = types[at];
            g_e[at] = v + (tt ? b12 : b02)[0];
        }
    }

    /* ---- bwd1: K split 32/32 ---- */
    const float* ga = sG[a0];
    const float* gb = sG[a1];
    float r0 = 0.f, r1 = 0.f;
    if (t0 == t1){
        const float* WT = g_W1T + (size_t)t0*HID*HID;
        #pragma unroll 8
        for (int q = 0; q < 32; q++){
            int ss = slo + q;
            float w = WT[ss*HID + j];
            r0 = fmaf(ga[ss], w, r0);
            r1 = fmaf(gb[ss], w, r1);
        }
    } else {
        const float* WTa = g_W1T + (size_t)t0*HID*HID;
        const float* WTb = g_W1T + (size_t)t1*HID*HID;
        #pragma unroll 8
        for (int q = 0; q < 32; q++){
            int ss = slo + q;
            r0 = fmaf(ga[ss], WTa[ss*HID + j], r0);
            r1 = fmaf(gb[ss], WTb[ss*HID + j], r1);
        }
    }
    ps[half][a0][j] = r0;
    ps[half][a1][j] = r1;
    __syncthreads();

    if (half == 0){
        sZ[a0][j] = (ps[0][a0][j] + ps[1][a0][j]) * (1.0f - h1a*h1a);
        sZ[a1][j] = (ps[0][a1][j] + ps[1][a1][j]) * (1.0f - h1b*h1b);
    }
    __syncthreads();

    /* ---- bwd2: d strided by 128 over both halves ---- */
    const float* z0 = sZ[a0];
    const float* z1 = sZ[a1];
    if (t0 == t1){
        const float* WT = g_W0T + (size_t)t0*HID*DDIM;
        for (int d = j + 64*half; d < DDIM; d += 128){
            float u0 = 0.f, u1 = 0.f;
            #pragma unroll 8
            for (int ss = 0; ss < HID; ss++){
                float w = WT[ss*DDIM + d];
                u0 = fmaf(z0[ss], w, u0);
                u1 = fmaf(z1[ss], w, u1);
            }
            g_gdesc[(size_t)atom0*DDIM + d] = u0;
            g_gdesc[(size_t)atom1*DDIM + d] = u1;
        }
    } else {
        const float* WTa = g_W0T + (size_t)t0*HID*DDIM;
        const float* WTb = g_W0T + (size_t)t1*HID*DDIM;
        for (int d = j + 64*half; d < DDIM; d += 128){
            float u0 = 0.f, u1 = 0.f;
            #pragma unroll 8
            for (int ss = 0; ss < HID; ss++){
                u0 = fmaf(z0[ss], WTa[ss*DDIM + d], u0);
                u1 = fmaf(z1[ss], WTb[ss*DDIM + d], u1);
            }
            g_gdesc[(size_t)atom0*DDIM + d] = u0;
            g_gdesc[(size_t)atom1*DDIM + d] = u1;
        }
    }
}

// ---------------------------------------------------------------------------
// K4: descriptor backward (warp per atom, 16 atoms / 512-thread block)
// ---------------------------------------------------------------------------
__global__ void __launch_bounds__(512, 2)
bwd_kernel(const float* __restrict__ xyz){
    __shared__ float4 sp[NA];
    int tid = threadIdx.x;
    int w = tid >> 5, lane = tid & 31;
    int atom = blockIdx.x*BWPB + w;
    int b = atom >> 11, i = atom & (NA-1);
    const float* xb = xyz + (size_t)b*NA*3;

    for (int j = tid; j < NA; j += BWPB*32)
        sp[j] = make_float4(xb[3*j+0], xb[3*j+1], xb[3*j+2], 0.0f);
    __syncthreads();

    float4 pi = sp[i];
    float xi = pi.x, yi = pi.y, zi = pi.z;

    /* cached frame */
    float4 f0 = g_frame[(size_t)atom*3 + 0];
    float4 f1 = g_frame[(size_t)atom*3 + 1];
    float4 f2 = g_frame[(size_t)atom*3 + 2];
    float rv0x = f0.x, rv0y = f0.y, rv0z = f0.z, d0 = f0.w;
    float rv1x = f1.x, rv1y = f1.y, rv1z = f1.z, d1 = f1.w;
    float np = f2.x, nc = f2.y;
    int j0 = __float_as_int(f2.z), j1 = __float_as_int(f2.w);

    float inv0 = 1.0f/(d0 + EPSF);
    float inv1 = 1.0f/(d1 + EPSF);
    float r0x = rv0x*inv0, r0y = rv0y*inv0, r0z = rv0z*inv0;
    float r1x = rv1x*inv1, r1y = rv1y*inv1, r1z = rv1z*inv1;

    float s = r0x*r1x + r0y*r1y + r0z*r1z;
    float px = r1x - s*r0x, py = r1y - s*r0y, pz = r1z - s*r0z;
    float invnp = 1.0f/np;
    float v2x = px*invnp, v2y = py*invnp, v2z = pz*invnp;

    float cx = r0y*r1z - r0z*r1y;
    float cy = r0z*r1x - r0x*r1z;
    float cz = r0x*r1y - r0y*r1x;
    float invnc = 1.0f/nc;
    float v3x = cx*invnc, v3y = cy*invnc, v3z = cz*invnc;

    const float* gd = g_gdesc + (size_t)atom*DDIM;
    float* gradb = g_grad + (size_t)b*NA*3;

    float G0=0,G1=0,G2=0,G3=0,G4=0,G5=0,G6=0,G7=0,G8=0;
    float gix=0, giy=0, giz=0;

    for (int k = lane; k < NANG; k += 32){
        int j; float dN;
        if (k < ASEL0){ j = g_idx0[(size_t)atom*SEL0 + k]; dN = g_dist0[(size_t)atom*SEL0 + k]; }
        else          { j = g_idx1[(size_t)atom*SEL1 + (k-ASEL0)]; dN = g_dist1[(size_t)atom*SEL1 + (k-ASEL0)]; }
        float4 p = sp[j];
        float rx = mic(xi - p.x + EPSF);
        float ry = mic(yi - p.y + EPSF);
        float rz = mic(zi - p.z + EPSF);
        float gx = gd[NRAD + 3*k + 0];
        float gy = gd[NRAD + 3*k + 1];
        float gz3= gd[NRAD + 3*k + 2];
        float inv = 1.0f/(dN + EPSF);
        float ww = inv*inv;
        float Arx = r0x*rx + r0y*ry + r0z*rz;
        float Ary = v2x*rx + v2y*ry + v2z*rz;
        float Arz = v3x*rx + v3y*ry + v3z*rz;
        float gvx = (r0x*gx + v2x*gy + v3x*gz3)*ww;
        float gvy = (r0y*gx + v2y*gy + v3y*gz3)*ww;
        float gvz = (r0z*gx + v2z*gy + v3z*gz3)*ww;
        float gdd = (gx*Arx + gy*Ary + gz3*Arz) * (-2.0f*ww*inv);
        G0 += ww*gx*rx;  G1 += ww*gx*ry;  G2 += ww*gx*rz;
        G3 += ww*gy*rx;  G4 += ww*gy*ry;  G5 += ww*gy*rz;
        G6 += ww*gz3*rx; G7 += ww*gz3*ry; G8 += ww*gz3*rz;
        float cf = gdd / dN;
        float gtx = gvx + cf*rx, gty = gvy + cf*ry, gtz = gvz + cf*rz;
        gix += gtx; giy += gty; giz += gtz;
        atomicAdd(&gradb[3*j+0], -gtx);
        atomicAdd(&gradb[3*j+1], -gty);
        atomicAdd(&gradb[3*j+2], -gtz);
    }

    for (int m = lane; m < NRAD; m += 32){
        int j; float sd;
        if (m < SEL0){ j = g_idx0[(size_t)atom*SEL0 + m]; sd = g_dist0[(size_t)atom*SEL0 + m]; }
        else         { j = g_idx1[(size_t)atom*SEL1 + (m-SEL0)]; sd = g_dist1[(size_t)atom*SEL1 + (m-SEL0)]; }
        float gR = gd[m];
        float invr = 1.0f/(sd + EPSF);
        float cf = -gR*invr*invr / sd;
        float4 p = sp[j];
        float rx = mic(xi - p.x + EPSF);
        float ry = mic(yi - p.y + EPSF);
        float rz = mic(zi - p.z + EPSF);
        float gtx = cf*rx, gty = cf*ry, gtz = cf*rz;
        gix += gtx; giy += gty; giz += gtz;
        atomicAdd(&gradb[3*j+0], -gtx);
        atomicAdd(&gradb[3*j+1], -gty);
        atomicAdd(&gradb[3*j+2], -gtz);
    }

    G0 = wred(G0); G1 = wred(G1); G2 = wred(G2);
    G3 = wred(G3); G4 = wred(G4); G5 = wred(G5);
    G6 = wred(G6); G7 = wred(G7); G8 = wred(G8);
    gix = wred(gix); giy = wred(giy); giz = wred(giz);

    if (lane == 0){
        float dr0x = G0, dr0y = G1, dr0z = G2;
        float dr1x = 0.f, dr1y = 0.f, dr1z = 0.f;

        float t1v = G3*v2x + G4*v2y + G5*v2z;
        float gpx = (G3 - t1v*v2x)*invnp;
        float gpy = (G4 - t1v*v2y)*invnp;
        float gpz = (G5 - t1v*v2z)*invnp;
        float gpr0 = gpx*r0x + gpy*r0y + gpz*r0z;
        dr1x += gpx - gpr0*r0x;
        dr1y += gpy - gpr0*r0y;
        dr1z += gpz - gpr0*r0z;
        dr0x += -s*gpx - gpr0*r1x;
        dr0y += -s*gpy - gpr0*r1y;
        dr0z += -s*gpz - gpr0*r1z;

        float t2v = G6*v3x + G7*v3y + G8*v3z;
        float gcx = (G6 - t2v*v3x)*invnc;
        float gcy = (G7 - t2v*v3y)*invnc;
        float gcz = (G8 - t2v*v3z)*invnc;
        dr0x += r1y*gcz - r1z*gcy;
        dr0y += r1z*gcx - r1x*gcz;
        dr0z += r1x*gcy - r1y*gcx;
        dr1x += gcy*r0z - gcz*r0y;
        dr1y += gcz*r0x - gcx*r0z;
        dr1z += gcx*r0y - gcy*r0x;

        float dd0 = (dr0x*rv0x + dr0y*rv0y + dr0z*rv0z) * (-inv0*inv0);
        float c0 = dd0 / d0;
        float gt0x = dr0x*inv0 + c0*rv0x;
        float gt0y = dr0y*inv0 + c0*rv0y;
        float gt0z = dr0z*inv0 + c0*rv0z;
        atomicAdd(&gradb[3*j0+0], -gt0x);
        atomicAdd(&gradb[3*j0+1], -gt0y);
        atomicAdd(&gradb[3*j0+2], -gt0z);

        float dd1 = (dr1x*rv1x + dr1y*rv1y + dr1z*rv1z) * (-inv1*inv1);
        float c1 = dd1 / d1;
        float gt1x = dr1x*inv1 + c1*rv1x;
        float gt1y = dr1y*inv1 + c1*rv1y;
        float gt1z = dr1z*inv1 + c1*rv1z;
        atomicAdd(&gradb[3*j1+0], -gt1x);
        atomicAdd(&gradb[3*j1+1], -gt1y);
        atomicAdd(&gradb[3*j1+2], -gt1z);

        atomicAdd(&gradb[3*i+0], gix + gt0x + gt1x);
        atomicAdd(&gradb[3*i+1], giy + gt0y + gt1y);
        atomicAdd(&gradb[3*i+2], giz + gt0z + gt1z);
    }
}

// ---------------------------------------------------------------------------
// Output
// ---------------------------------------------------------------------------
__global__ void out_kernel(float* __restrict__ out){
    if (blockIdx.x < 48){
        int idx = blockIdx.x*256 + threadIdx.x;
        if (idx < NATOMS*3) out[2 + idx] = -g_grad[idx];
    } else {
        __shared__ float red[256];
        int b = blockIdx.x - 48;
        int tid = threadIdx.x;
        float acc = 0.0f;
        for (int i2 = tid; i2 < NA; i2 += 256) acc += g_e[b*NA + i2];
        red[tid] = acc;
        __syncthreads();
        for (int off = 128; off > 0; off >>= 1){
            if (tid < off) red[tid] += red[tid + off];
            __syncthreads();
        }
        if (tid == 0) out[b] = red[0];
    }
}

// ---------------------------------------------------------------------------
extern "C" void kernel_launch(void* const* d_in, const int* in_sizes, int n_in,
                              void* d_out, int out_size){
    const float* xyz   = (const float*)d_in[0];
    const int*   types = (const int*)  d_in[1];
    const float* W00=(const float*)d_in[3],  *b00=(const float*)d_in[4];
    const float* W01=(const float*)d_in[5],  *b01=(const float*)d_in[6];
    const float* W02=(const float*)d_in[7],  *b02=(const float*)d_in[8];
    const float* W10=(const float*)d_in[9],  *b10=(const float*)d_in[10];
    const float* W11=(const float*)d_in[11], *b11=(const float*)d_in[12];
    const float* W12=(const float*)d_in[13], *b12=(const float*)d_in[14];
    float* out = (float*)d_out;

    void* cptr = 0;
    cudaGetSymbolAddress(&cptr, g_cnt);
    cudaMemsetAsync(cptr, 0, 2*sizeof(int));

    prep_kernel<<<(2*DDIM*HID + 255)/256, 256>>>(types, W00, W10, W01, W11); /* 1 */
    knnd_kernel<<<NATOMS/WPB, WPB*32>>>(xyz, types);                         /* 2 */
    mlp_kernel<<<NATOMS/APB, 512>>>(types, W00,b00,W01,b01,W02,b02,          /* 3 */
                                           W10,b10,W11,b11,W12,b12);
    bwd_kernel<<<NATOMS/BWPB, BWPB*32>>>(xyz);                               /* 4: profiled */
    out_kernel<<<50, 256>>>(out);                                            /* 5 */
}

// round 15
// speedup vs baseline: 1.0377x; 1.0377x over previous
#include <cuda_runtime.h>
#include <math.h>

#define BB 2
#define NA 2048
#define NATOMS (BB*NA)
#define BOXF 27.0f
#define SEL0 46
#define SEL1 92
#define ASEL0 16
#define ASEL1 32
#define NANG (ASEL0+ASEL1)      /* 48  */
#define NRAD (SEL0+SEL1)        /* 138 */
#define DDIM (NRAD + 3*NANG)    /* 282 */
#define HID 64
#define EPSF 1e-16f
#define FULLM 0xFFFFFFFFu

#define WPB 8
#define BWPB 16               /* atoms per block in bwd (512 threads) */
#define NBINW 128
#define BSCALEW 9.375f
#define CAPW0 96
#define CAPW1 160

__device__ float g_dist0[NATOMS*SEL0];
__device__ int   g_idx0 [NATOMS*SEL0];
__device__ float g_dist1[NATOMS*SEL1];
__device__ int   g_idx1 [NATOMS*SEL1];
__device__ float4 g_frame[NATOMS*3];
__device__ float g_desc [NATOMS*DDIM];
__device__ float g_gdesc[NATOMS*DDIM];
__device__ float g_grad [NATOMS*3];
__device__ float g_e    [NATOMS];
__device__ float g_W0T  [2*HID*DDIM];
__device__ float g_W1T  [2*HID*HID];
__device__ int   g_perm [NATOMS];
__device__ int   g_cnt  [2];

__device__ __forceinline__ float mic(float d){
    return d - BOXF * rintf(d * (1.0f/BOXF));
}
__device__ __forceinline__ float wred(float v){
    v += __shfl_xor_sync(FULLM, v, 16);
    v += __shfl_xor_sync(FULLM, v, 8);
    v += __shfl_xor_sync(FULLM, v, 4);
    v += __shfl_xor_sync(FULLM, v, 2);
    v += __shfl_xor_sync(FULLM, v, 1);
    return v;
}
__device__ __forceinline__ void wmin2(float &d, int &i){
    #pragma unroll
    for (int off = 16; off > 0; off >>= 1){
        float od = __shfl_xor_sync(FULLM, d, off);
        int   oi = __shfl_xor_sync(FULLM, i, off);
        if (od < d){ d = od; i = oi; }
    }
}

// ---------------------------------------------------------------------------
// Prep: weight transposes + grad zero + type-partition permutation (fused)
// ---------------------------------------------------------------------------
__global__ void prep_kernel(const int* __restrict__ types,
    const float* __restrict__ W00, const float* __restrict__ W10,
    const float* __restrict__ W01, const float* __restrict__ W11){
    __shared__ int wb[8][2];
    int tid = threadIdx.x;
    int idx = blockIdx.x*blockDim.x + tid;
    if (idx < 2*DDIM*HID){
        int t = idx / (DDIM*HID);
        int r = idx % (DDIM*HID);
        int d = r / HID, s = r % HID;
        const float* W = t ? W10 : W00;
        g_W0T[t*HID*DDIM + s*DDIM + d] = W[r];
    }
    if (idx < 2*HID*HID){
        int t = idx / (HID*HID);
        int r = idx % (HID*HID);
        int c = r / HID, s = r % HID;
        const float* W = t ? W11 : W01;
        g_W1T[t*HID*HID + s*HID + c] = W[r];
    }
    if (idx < NATOMS*3) g_grad[idx] = 0.0f;
    if (idx < NATOMS){
        int lane = tid & 31, w = tid >> 5;
        unsigned lanelt = (1u << lane) - 1u;
        int t = types[idx];
        unsigned m0 = __ballot_sync(FULLM, t == 0);
        int n0 = __popc(m0);
        if (lane == 0){
            wb[w][0] = atomicAdd(&g_cnt[0], n0);
            wb[w][1] = atomicAdd(&g_cnt[1], 32 - n0);
        }
        __syncwarp();
        int pos = (t == 0) ? (wb[w][0] + __popc(m0 & lanelt))
                           : (NATOMS - 1 - (wb[w][1] + __popc(~m0 & lanelt)));
        g_perm[pos] = idx;
    }
}

// ---------------------------------------------------------------------------
// K1: fused warp-per-atom kNN (histogram select) + descriptor fwd + frame out
// ---------------------------------------------------------------------------
__global__ void knnd_kernel(const float* __restrict__ xyz, const int* __restrict__ types){
    __shared__ float4 sp[NA];
    __shared__ unsigned int hist[WPB][NBINW];
    __shared__ unsigned long long c0buf[WPB][CAPW0];
    __shared__ unsigned long long c1buf[WPB][CAPW1];

    int tid = threadIdx.x;
    int w = tid >> 5, lane = tid & 31;
    int atom = blockIdx.x*WPB + w;
    int b = atom >> 11, i = atom & (NA-1);
    const float* xb = xyz + (size_t)b*NA*3;
    const int* tb = types + (size_t)b*NA;

    for (int j = tid; j < NA; j += WPB*32)
        sp[j] = make_float4(xb[3*j+0], xb[3*j+1], xb[3*j+2], __int_as_float(tb[j]));
    __syncthreads();

    float4 pi = sp[i];
    float xi = pi.x, yi = pi.y, zi = pi.z;

    #pragma unroll
    for (int q = 0; q < NBINW/32; q++) hist[w][lane + 32*q] = 0;
    __syncwarp();

    /* pass 1: packed histogram */
    for (int j = lane; j < NA; j += 32){
        if (j == i) continue;
        float4 p = sp[j];
        float dx = mic(xi - p.x + EPSF);
        float dy = mic(yi - p.y + EPSF);
        float dz = mic(zi - p.z + EPSF);
        float d = sqrtf(dx*dx + dy*dy + dz*dz);
        int bn = (int)(d * BSCALEW); if (bn > NBINW-1) bn = NBINW-1;
        atomicAdd(&hist[w][bn], __float_as_int(p.w) ? 0x10000u : 1u);
    }
    __syncwarp();

    /* threshold scan */
    unsigned chunk = 0;
    #pragma unroll
    for (int q = 0; q < 4; q++) chunk += hist[w][4*lane + q];
    unsigned incl = chunk;
    #pragma unroll
    for (int off = 1; off < 32; off <<= 1){
        unsigned v = __shfl_up_sync(FULLM, incl, off);
        if (lane >= off) incl += v;
    }
    unsigned excl = incl - chunk;

    int thr0, thr1;
    {
        unsigned m0 = __ballot_sync(FULLM, (incl & 0xFFFFu) >= SEL0);
        int fl = __ffs(m0) - 1;
        int tl = 0;
        if (lane == fl){
            int c = (int)(excl & 0xFFFFu);
            int bq = 4*lane;
            #pragma unroll
            for (int q = 0; q < 4; q++){
                c += (int)(hist[w][bq] & 0xFFFFu);
                if (c >= SEL0) break;
                bq++;
            }
            tl = bq;
        }
        thr0 = __shfl_sync(FULLM, tl, fl);
    }
    {
        unsigned m1 = __ballot_sync(FULLM, (incl >> 16) >= SEL1);
        int fl = __ffs(m1) - 1;
        int tl = 0;
        if (lane == fl){
            int c = (int)(excl >> 16);
            int bq = 4*lane;
            #pragma unroll
            for (int q = 0; q < 4; q++){
                c += (int)(hist[w][bq] >> 16);
                if (c >= SEL1) break;
                bq++;
            }
            tl = bq;
        }
        thr1 = __shfl_sync(FULLM, tl, fl);
    }

    /* pass 2: ballot compaction */
    unsigned lanelt = (1u << lane) - 1u;
    int cnt0 = 0, cnt1 = 0;
    for (int j = lane; j < NA; j += 32){
        float4 p = sp[j];
        int t = (j == i) ? 2 : __float_as_int(p.w);
        float dx = mic(xi - p.x + EPSF);
        float dy = mic(yi - p.y + EPSF);
        float dz = mic(zi - p.z + EPSF);
        float d = sqrtf(dx*dx + dy*dy + dz*dz);
        int bn = (int)(d * BSCALEW); if (bn > NBINW-1) bn = NBINW-1;
        unsigned long long key = ((unsigned long long)__float_as_uint(d) << 11)
                               | (unsigned long long)j;
        bool p0 = (t == 0) && (bn <= thr0);
        bool p1 = (t == 1) && (bn <= thr1);
        unsigned m0 = __ballot_sync(FULLM, p0);
        unsigned m1 = __ballot_sync(FULLM, p1);
        if (p0){ int pos = cnt0 + __popc(m0 & lanelt); if (pos < CAPW0) c0buf[w][pos] = key; }
        if (p1){ int pos = cnt1 + __popc(m1 & lanelt); if (pos < CAPW1) c1buf[w][pos] = key; }
        cnt0 += __popc(m0); cnt1 += __popc(m1);
    }
    if (cnt0 > CAPW0) cnt0 = CAPW0;
    if (cnt1 > CAPW1) cnt1 = CAPW1;
    __syncwarp();

    /* rank sort + write; capture top-2 per type via shuffle-argmin */
    float t0d0 = INFINITY, t0d1 = INFINITY; int t0i0 = 0, t0i1 = 0;
    float t1d0 = INFINITY, t1d1 = INFINITY; int t1i0 = 0, t1i1 = 0;

    for (int m = lane; m < cnt0; m += 32){
        unsigned long long k64 = c0buf[w][m];
        int r = 0;
        for (int q = 0; q < cnt0; q++) r += (c0buf[w][q] < k64);
        float dv = __uint_as_float((unsigned)(k64 >> 11));
        int jv = (int)(k64 & 2047ULL);
        if (r == 0){ t0d0 = dv; t0i0 = jv; }
        else if (r == 1){ t0d1 = dv; t0i1 = jv; }
        if (r < SEL0){
            g_dist0[(size_t)atom*SEL0 + r] = dv;
            g_idx0 [(size_t)atom*SEL0 + r] = jv;
        }
    }
    for (int m = lane; m < cnt1; m += 32){
        unsigned long long k64 = c1buf[w][m];
        int r = 0;
        for (int q = 0; q < cnt1; q++) r += (c1buf[w][q] < k64);
        float dv = __uint_as_float((unsigned)(k64 >> 11));
        int jv = (int)(k64 & 2047ULL);
        if (r == 0){ t1d0 = dv; t1i0 = jv; }
        else if (r == 1){ t1d1 = dv; t1i1 = jv; }
        if (r < SEL1){
            g_dist1[(size_t)atom*SEL1 + r] = dv;
            g_idx1 [(size_t)atom*SEL1 + r] = jv;
        }
    }
    __threadfence_block();
    __syncwarp();

    wmin2(t0d0, t0i0); wmin2(t0d1, t0i1);
    wmin2(t1d0, t1i0); wmin2(t1d1, t1i1);

    /* ---- local frame (uniform across warp) ---- */
    float d0, d1; int j0, j1;
    if (t1d0 < t0d0){ d0 = t1d0; j0 = t1i0; } else { d0 = t0d0; j0 = t0i0; }
    if (t1d1 < t0d1){ d1 = t1d1; j1 = t1i1; } else { d1 = t0d1; j1 = t0i1; }

    float4 pj0 = sp[j0], pj1 = sp[j1];
    float rv0x = mic(xi - pj0.x + EPSF);
    float rv0y = mic(yi - pj0.y + EPSF);
    float rv0z = mic(zi - pj0.z + EPSF);
    float rv1x = mic(xi - pj1.x + EPSF);
    float rv1y = mic(yi - pj1.y + EPSF);
    float rv1z = mic(zi - pj1.z + EPSF);

    float inv0 = 1.0f/(d0 + EPSF);
    float inv1 = 1.0f/(d1 + EPSF);
    float r0x = rv0x*inv0, r0y = rv0y*inv0, r0z = rv0z*inv0;
    float r1x = rv1x*inv1, r1y = rv1y*inv1, r1z = rv1z*inv1;

    float s = r0x*r1x + r0y*r1y + r0z*r1z;
    float px = r1x - s*r0x, py = r1y - s*r0y, pz = r1z - s*r0z;
    float np = sqrtf(px*px + py*py + pz*pz);
    float invnp = 1.0f/np;
    float v2x = px*invnp, v2y = py*invnp, v2z = pz*invnp;

    float cx = r0y*r1z - r0z*r1y;
    float cy = r0z*r1x - r0x*r1z;
    float cz = r0x*r1y - r0y*r1x;
    float nc = sqrtf(cx*cx + cy*cy + cz*cz);
    float invnc = 1.0f/nc;
    float v3x = cx*invnc, v3y = cy*invnc, v3z = cz*invnc;

    if (lane == 0){
        g_frame[(size_t)atom*3 + 0] = make_float4(rv0x, rv0y, rv0z, d0);
        g_frame[(size_t)atom*3 + 1] = make_float4(rv1x, rv1y, rv1z, d1);
        g_frame[(size_t)atom*3 + 2] = make_float4(np, nc,
                                     __int_as_float(j0), __int_as_float(j1));
    }

    /* ---- descriptor ---- */
    float* dsc = g_desc + (size_t)atom*DDIM;
    for (int m = lane; m < NRAD; m += 32){
        float sd = (m < SEL0) ? g_dist0[(size_t)atom*SEL0 + m]
                              : g_dist1[(size_t)atom*SEL1 + (m - SEL0)];
        dsc[m] = 1.0f/(sd + EPSF);
    }
    for (int k = lane; k < NANG; k += 32){
        int j; float d;
        if (k < ASEL0){ j = g_idx0[(size_t)atom*SEL0 + k]; d = g_dist0[(size_t)atom*SEL0 + k]; }
        else          { j = g_idx1[(size_t)atom*SEL1 + (k-ASEL0)]; d = g_dist1[(size_t)atom*SEL1 + (k-ASEL0)]; }
        float4 p = sp[j];
        float rx = mic(xi - p.x + EPSF);
        float ry = mic(yi - p.y + EPSF);
        float rz = mic(zi - p.z + EPSF);
        float inv = 1.0f/(d + EPSF);
        float ww = inv*inv;
        dsc[NRAD + 3*k + 0] = (r0x*rx + r0y*ry + r0z*rz)*ww;
        dsc[NRAD + 3*k + 1] = (v2x*rx + v2y*ry + v2z*rz)*ww;
        dsc[NRAD + 3*k + 2] = (v3x*rx + v3y*ry + v3z*rz)*ww;
    }
}

// ---------------------------------------------------------------------------
// K3: fused MLP fwd+bwd, K-split across two thread-halves (block = 512)
// ---------------------------------------------------------------------------
#define APB 8

__global__ void mlp_kernel(const int* __restrict__ types,
    const float* __restrict__ W00, const float* __restrict__ b00,
    const float* __restrict__ W01, const float* __restrict__ b01,
    const float* __restrict__ W02, const float* __restrict__ b02,
    const float* __restrict__ W10, const float* __restrict__ b10,
    const float* __restrict__ W11, const float* __restrict__ b11,
    const float* __restrict__ W12, const float* __restrict__ b12){

    __shared__ int   satom[APB];
    __shared__ float sX[APB][DDIM];
    __shared__ float ps[2][APB][HID];
    __shared__ float sH1[APB][HID];
    __shared__ float sG[APB][HID];
    __shared__ float sZ[APB][HID];
    __shared__ float red[APB][HID];

    int tid = threadIdx.x;               /* 0..511 */
    int j = tid & (HID-1);
    int g = (tid >> 6) & 3;
    int half = tid >> 8;                 /* 0 or 1 */
    int base = blockIdx.x * APB;

    if (tid < APB) satom[tid] = g_perm[base + tid];
    __syncthreads();

    for (int d = tid; d < APB*DDIM; d += 512){
        int aa = d / DDIM, dd = d % DDIM;
        sX[aa][dd] = g_desc[(size_t)satom[aa]*DDIM + dd];
    }
    __syncthreads();

    int a0 = 2*g, a1 = 2*g+1;
    int atom0 = satom[a0], atom1 = satom[a1];
    int t0 = types[atom0], t1 = types[atom1];
    const float* x0 = sX[a0];
    const float* x1 = sX[a1];

    /* ---- layer 1: K split [0,142) / [142,282) ---- */
    int dlo = half ? 142 : 0;
    int dhi = half ? DDIM : 142;
    float p0, p1;
    if (t0 == t1){
        const float* W = t0 ? W10 : W00;
        float e0 = 0.f, e1 = 0.f, o0 = 0.f, o1 = 0.f;
        #pragma unroll 4
        for (int d = dlo; d < dhi; d += 2){
            float w0 = W[d*HID + j];
            float w1 = W[(d+1)*HID + j];
            e0 = fmaf(x0[d],   w0, e0);
            e1 = fmaf(x1[d],   w0, e1);
            o0 = fmaf(x0[d+1], w1, o0);
            o1 = fmaf(x1[d+1], w1, o1);
        }
        p0 = e0 + o0; p1 = e1 + o1;
    } else {
        const float* Wa = t0 ? W10 : W00;
        const float* Wb = t1 ? W10 : W00;
        float e0 = 0.f, e1 = 0.f, o0 = 0.f, o1 = 0.f;
        #pragma unroll 2
        for (int d = dlo; d < dhi; d += 2){
            e0 = fmaf(x0[d],   Wa[d*HID + j],     e0);
            e1 = fmaf(x1[d],   Wb[d*HID + j],     e1);
            o0 = fmaf(x0[d+1], Wa[(d+1)*HID + j], o0);
            o1 = fmaf(x1[d+1], Wb[(d+1)*HID + j], o1);
        }
        p0 = e0 + o0; p1 = e1 + o1;
    }
    ps[half][a0][j] = p0;
    ps[half][a1][j] = p1;
    __syncthreads();

    float h1a = 0.f, h1b = 0.f;
    if (half == 0){
        h1a = tanhf(ps[0][a0][j] + ps[1][a0][j] + (t0 ? b10 : b00)[j]);
        h1b = tanhf(ps[0][a1][j] + ps[1][a1][j] + (t1 ? b10 : b00)[j]);
        sH1[a0][j] = h1a;
        sH1[a1][j] = h1b;
    }
    __syncthreads();

    /* ---- layer 2: K split 32/32 ---- */
    int slo = half*32;
    const float* h0 = sH1[a0];
    const float* h1r = sH1[a1];
    float q0 = 0.f, q1 = 0.f;
    if (t0 == t1){
        const float* W = t0 ? W11 : W01;
        #pragma unroll 8
        for (int q = 0; q < 32; q++){
            int ss = slo + q;
            float w = W[ss*HID + j];
            q0 = fmaf(h0[ss],  w, q0);
            q1 = fmaf(h1r[ss], w, q1);
        }
    } else {
        const float* Wa = t0 ? W11 : W01;
        const float* Wb = t1 ? W11 : W01;
        #pragma unroll 8
        for (int q = 0; q < 32; q++){
            int ss = slo + q;
            q0 = fmaf(h0[ss],  Wa[ss*HID + j], q0);
            q1 = fmaf(h1r[ss], Wb[ss*HID + j], q1);
        }
    }
    ps[half][a0][j] = q0;
    ps[half][a1][j] = q1;
    __syncthreads();

    if (half == 0){
        float h2a = tanhf(ps[0][a0][j] + ps[1][a0][j] + (t0 ? b11 : b01)[j]);
        float h2b = tanhf(ps[0][a1][j] + ps[1][a1][j] + (t1 ? b11 : b01)[j]);
        float w2a = (t0 ? W12 : W02)[j];
        float w2b = (t1 ? W12 : W02)[j];
        red[a0][j] = h2a * w2a;
        red[a1][j] = h2b * w2b;
        sG[a0][j] = w2a * (1.0f - h2a*h2a);
        sG[a1][j] = w2b * (1.0f - h2b*h2b);
    }
    __syncthreads();

    /* energy reduce on first 8 warps */
    if (half == 0){
        int ww = tid >> 5, lane = tid & 31;
        float v = red[ww][lane] + red[ww][lane+32];
        v = wred(v);
        if (lane == 0){
            int at = satom[ww];
            int tt = types[at];
            g_e[at] = v + (tt ? b12 : b02)[0];
        }
    }

    /* ---- bwd1: K split 32/32 ---- */
    const float* ga = sG[a0];
    const float* gb = sG[a1];
    float r0 = 0.f, r1 = 0.f;
    if (t0 == t1){
        const float* WT = g_W1T + (size_t)t0*HID*HID;
        #pragma unroll 8
        for (int q = 0; q < 32; q++){
            int ss = slo + q;
            float w = WT[ss*HID + j];
            r0 = fmaf(ga[ss], w, r0);
            r1 = fmaf(gb[ss], w, r1);
        }
    } else {
        const float* WTa = g_W1T + (size_t)t0*HID*HID;
        const float* WTb = g_W1T + (size_t)t1*HID*HID;
        #pragma unroll 8
        for (int q = 0; q < 32; q++){
            int ss = slo + q;
            r0 = fmaf(ga[ss], WTa[ss*HID + j], r0);
            r1 = fmaf(gb[ss], WTb[ss*HID + j], r1);
        }
    }
    ps[half][a0][j] = r0;
    ps[half][a1][j] = r1;
    __syncthreads();

    if (half == 0){
        sZ[a0][j] = (ps[0][a0][j] + ps[1][a0][j]) * (1.0f - h1a*h1a);
        sZ[a1][j] = (ps[0][a1][j] + ps[1][a1][j]) * (1.0f - h1b*h1b);
    }
    __syncthreads();

    /* ---- bwd2: d strided by 128 over both halves ---- */
    const float* z0 = sZ[a0];
    const float* z1 = sZ[a1];
    if (t0 == t1){
        const float* WT = g_W0T + (size_t)t0*HID*DDIM;
        for (int d = j + 64*half; d < DDIM; d += 128){
            float u0 = 0.f, u1 = 0.f;
            #pragma unroll 8
            for (int ss = 0; ss < HID; ss++){
                float w = WT[ss*DDIM + d];
                u0 = fmaf(z0[ss], w, u0);
                u1 = fmaf(z1[ss], w, u1);
            }
            g_gdesc[(size_t)atom0*DDIM + d] = u0;
            g_gdesc[(size_t)atom1*DDIM + d] = u1;
        }
    } else {
        const float* WTa = g_W0T + (size_t)t0*HID*DDIM;
        const float* WTb = g_W0T + (size_t)t1*HID*DDIM;
        for (int d = j + 64*half; d < DDIM; d += 128){
            float u0 = 0.f, u1 = 0.f;
            #pragma unroll 8
            for (int ss = 0; ss < HID; ss++){
                u0 = fmaf(z0[ss], WTa[ss*DDIM + d], u0);
                u1 = fmaf(z1[ss], WTb[ss*DDIM + d], u1);
            }
            g_gdesc[(size_t)atom0*DDIM + d] = u0;
            g_gdesc[(size_t)atom1*DDIM + d] = u1;
        }
    }
}

// ---------------------------------------------------------------------------
// K4: descriptor backward — single merged loop, one atomic triple per neighbor
// ---------------------------------------------------------------------------
__global__ void __launch_bounds__(512, 2)
bwd_kernel(const float* __restrict__ xyz){
    __shared__ float4 sp[NA];
    int tid = threadIdx.x;
    int w = tid >> 5, lane = tid & 31;
    int atom = blockIdx.x*BWPB + w;
    int b = atom >> 11, i = atom & (NA-1);
    const float* xb = xyz + (size_t)b*NA*3;

    for (int j = tid; j < NA; j += BWPB*32)
        sp[j] = make_float4(xb[3*j+0], xb[3*j+1], xb[3*j+2], 0.0f);
    __syncthreads();

    float4 pi = sp[i];
    float xi = pi.x, yi = pi.y, zi = pi.z;

    /* cached frame */
    float4 f0 = g_frame[(size_t)atom*3 + 0];
    float4 f1 = g_frame[(size_t)atom*3 + 1];
    float4 f2 = g_frame[(size_t)atom*3 + 2];
    float rv0x = f0.x, rv0y = f0.y, rv0z = f0.z, d0 = f0.w;
    float rv1x = f1.x, rv1y = f1.y, rv1z = f1.z, d1 = f1.w;
    float np = f2.x, nc = f2.y;
    int j0 = __float_as_int(f2.z), j1 = __float_as_int(f2.w);

    float inv0 = 1.0f/(d0 + EPSF);
    float inv1 = 1.0f/(d1 + EPSF);
    float r0x = rv0x*inv0, r0y = rv0y*inv0, r0z = rv0z*inv0;
    float r1x = rv1x*inv1, r1y = rv1y*inv1, r1z = rv1z*inv1;

    float s = r0x*r1x + r0y*r1y + r0z*r1z;
    float px = r1x - s*r0x, py = r1y - s*r0y, pz = r1z - s*r0z;
    float invnp = 1.0f/np;
    float v2x = px*invnp, v2y = py*invnp, v2z = pz*invnp;

    float cx = r0y*r1z - r0z*r1y;
    float cy = r0z*r1x - r0x*r1z;
    float cz = r0x*r1y - r0y*r1x;
    float invnc = 1.0f/nc;
    float v3x = cx*invnc, v3y = cy*invnc, v3z = cz*invnc;

    const float* gd = g_gdesc + (size_t)atom*DDIM;
    float* gradb = g_grad + (size_t)b*NA*3;

    float G0=0,G1=0,G2=0,G3=0,G4=0,G5=0,G6=0,G7=0,G8=0;
    float gix=0, giy=0, giz=0;

    /* merged radial + angular loop over the 138 selected neighbors */
    for (int m = lane; m < NRAD; m += 32){
        int j; float sd; int k;
        if (m < SEL0){
            j = g_idx0[(size_t)atom*SEL0 + m];
            sd = g_dist0[(size_t)atom*SEL0 + m];
            k = (m < ASEL0) ? m : -1;
        } else {
            int mm = m - SEL0;
            j = g_idx1[(size_t)atom*SEL1 + mm];
            sd = g_dist1[(size_t)atom*SEL1 + mm];
            k = (mm < ASEL1) ? (ASEL0 + mm) : -1;
        }
        float4 p = sp[j];
        float rx = mic(xi - p.x + EPSF);
        float ry = mic(yi - p.y + EPSF);
        float rz = mic(zi - p.z + EPSF);
        float invr = 1.0f/(sd + EPSF);

        /* radial term */
        float gR = gd[m];
        float cfr = -gR*invr*invr / sd;
        float gtx = cfr*rx, gty = cfr*ry, gtz = cfr*rz;

        /* angular term (first ASEL of each type list) */
        if (k >= 0){
            float gx = gd[NRAD + 3*k + 0];
            float gy = gd[NRAD + 3*k + 1];
            float gz3= gd[NRAD + 3*k + 2];
            float ww = invr*invr;
            float Arx = r0x*rx + r0y*ry + r0z*rz;
            float Ary = v2x*rx + v2y*ry + v2z*rz;
            float Arz = v3x*rx + v3y*ry + v3z*rz;
            float gvx = (r0x*gx + v2x*gy + v3x*gz3)*ww;
            float gvy = (r0y*gx + v2y*gy + v3y*gz3)*ww;
            float gvz = (r0z*gx + v2z*gy + v3z*gz3)*ww;
            float gdd = (gx*Arx + gy*Ary + gz3*Arz) * (-2.0f*ww*invr);
            G0 += ww*gx*rx;  G1 += ww*gx*ry;  G2 += ww*gx*rz;
            G3 += ww*gy*rx;  G4 += ww*gy*ry;  G5 += ww*gy*rz;
            G6 += ww*gz3*rx; G7 += ww*gz3*ry; G8 += ww*gz3*rz;
            float cfa = gdd / sd;
            gtx += gvx + cfa*rx;
            gty += gvy + cfa*ry;
            gtz += gvz + cfa*rz;
        }

        gix += gtx; giy += gty; giz += gtz;
        atomicAdd(&gradb[3*j+0], -gtx);
        atomicAdd(&gradb[3*j+1], -gty);
        atomicAdd(&gradb[3*j+2], -gtz);
    }

    G0 = wred(G0); G1 = wred(G1); G2 = wred(G2);
    G3 = wred(G3); G4 = wred(G4); G5 = wred(G5);
    G6 = wred(G6); G7 = wred(G7); G8 = wred(G8);
    gix = wred(gix); giy = wred(giy); giz = wred(giz);

    if (lane == 0){
        float dr0x = G0, dr0y = G1, dr0z = G2;
        float dr1x = 0.f, dr1y = 0.f, dr1z = 0.f;

        float t1v = G3*v2x + G4*v2y + G5*v2z;
        float gpx = (G3 - t1v*v2x)*invnp;
        float gpy = (G4 - t1v*v2y)*invnp;
        float gpz = (G5 - t1v*v2z)*invnp;
        float gpr0 = gpx*r0x + gpy*r0y + gpz*r0z;
        dr1x += gpx - gpr0*r0x;
        dr1y += gpy - gpr0*r0y;
        dr1z += gpz - gpr0*r0z;
        dr0x += -s*gpx - gpr0*r1x;
        dr0y += -s*gpy - gpr0*r1y;
        dr0z += -s*gpz - gpr0*r1z;

        float t2v = G6*v3x + G7*v3y + G8*v3z;
        float gcx = (G6 - t2v*v3x)*invnc;
        float gcy = (G7 - t2v*v3y)*invnc;
        float gcz = (G8 - t2v*v3z)*invnc;
        dr0x += r1y*gcz - r1z*gcy;
        dr0y += r1z*gcx - r1x*gcz;
        dr0z += r1x*gcy - r1y*gcx;
        dr1x += gcy*r0z - gcz*r0y;
        dr1y += gcz*r0x - gcx*r0z;
        dr1z += gcx*r0y - gcy*r0x;

        float dd0 = (dr0x*rv0x + dr0y*rv0y + dr0z*rv0z) * (-inv0*inv0);
        float c0 = dd0 / d0;
        float gt0x = dr0x*inv0 + c0*rv0x;
        float gt0y = dr0y*inv0 + c0*rv0y;
        float gt0z = dr0z*inv0 + c0*rv0z;
        atomicAdd(&gradb[3*j0+0], -gt0x);
        atomicAdd(&gradb[3*j0+1], -gt0y);
        atomicAdd(&gradb[3*j0+2], -gt0z);

        float dd1 = (dr1x*rv1x + dr1y*rv1y + dr1z*rv1z) * (-inv1*inv1);
        float c1 = dd1 / d1;
        float gt1x = dr1x*inv1 + c1*rv1x;
        float gt1y = dr1y*inv1 + c1*rv1y;
        float gt1z = dr1z*inv1 + c1*rv1z;
        atomicAdd(&gradb[3*j1+0], -gt1x);
        atomicAdd(&gradb[3*j1+1], -gt1y);
        atomicAdd(&gradb[3*j1+2], -gt1z);

        atomicAdd(&gradb[3*i+0], gix + gt0x + gt1x);
        atomicAdd(&gradb[3*i+1], giy + gt0y + gt1y);
        atomicAdd(&gradb[3*i+2], giz + gt0z + gt1z);
    }
}

// ---------------------------------------------------------------------------
// Output
// ---------------------------------------------------------------------------
__global__ void out_kernel(float* __restrict__ out){
    if (blockIdx.x < 48){
        int idx = blockIdx.x*256 + threadIdx.x;
        if (idx < NATOMS*3) out[2 + idx] = -g_grad[idx];
    } else {
        __shared__ float red[256];
        int b = blockIdx.x - 48;
        int tid = threadIdx.x;
        float acc = 0.0f;
        for (int i2 = tid; i2 < NA; i2 += 256) acc += g_e[b*NA + i2];
        red[tid] = acc;
        __syncthreads();
        for (int off = 128; off > 0; off >>= 1){
            if (tid < off) red[tid] += red[tid + off];
            __syncthreads();
        }
        if (tid == 0) out[b] = red[0];
    }
}

// ---------------------------------------------------------------------------
extern "C" void kernel_launch(void* const* d_in, const int* in_sizes, int n_in,
                              void* d_out, int out_size){
    const float* xyz   = (const float*)d_in[0];
    const int*   types = (const int*)  d_in[1];
    const float* W00=(const float*)d_in[3],  *b00=(const float*)d_in[4];
    const float* W01=(const float*)d_in[5],  *b01=(const float*)d_in[6];
    const float* W02=(const float*)d_in[7],  *b02=(const float*)d_in[8];
    const float* W10=(const float*)d_in[9],  *b10=(const float*)d_in[10];
    const float* W11=(const float*)d_in[11], *b11=(const float*)d_in[12];
    const float* W12=(const float*)d_in[13], *b12=(const float*)d_in[14];
    float* out = (float*)d_out;

    void* cptr = 0;
    cudaGetSymbolAddress(&cptr, g_cnt);
    cudaMemsetAsync(cptr, 0, 2*sizeof(int));

    prep_kernel<<<(2*DDIM*HID + 255)/256, 256>>>(types, W00, W10, W01, W11); /* 1 */
    knnd_kernel<<<NATOMS/WPB, WPB*32>>>(xyz, types);                         /* 2 */
    mlp_kernel<<<NATOMS/APB, 512>>>(types, W00,b00,W01,b01,W02,b02,          /* 3 */
                                           W10,b10,W11,b11,W12,b12);
    bwd_kernel<<<NATOMS/BWPB, BWPB*32>>>(xyz);                               /* 4: profiled */
    out_kernel<<<50, 256>>>(out);                                            /* 5 */
}

// round 16
// speedup vs baseline: 1.0832x; 1.0438x over previous
#include <cuda_runtime.h>
#include <math.h>

#define BB 2
#define NA 2048
#define NATOMS (BB*NA)
#define BOXF 27.0f
#define SEL0 46
#define SEL1 92
#define ASEL0 16
#define ASEL1 32
#define NANG (ASEL0+ASEL1)      /* 48  */
#define NRAD (SEL0+SEL1)        /* 138 */
#define DDIM (NRAD + 3*NANG)    /* 282 */
#define HID 64
#define EPSF 1e-16f
#define FULLM 0xFFFFFFFFu

#define WPB 8
#define BWPB 16
#define NBINW 128
#define BSCALE2 0.234f        /* 128 bins over d^2 in [0, 547] */
#define CAPW0 96
#define CAPW1 160

__device__ float g_dist0[NATOMS*SEL0];
__device__ int   g_idx0 [NATOMS*SEL0];
__device__ float g_dist1[NATOMS*SEL1];
__device__ int   g_idx1 [NATOMS*SEL1];
__device__ float4 g_frame[NATOMS*3];
__device__ float g_desc [NATOMS*DDIM];
__device__ float g_gdesc[NATOMS*DDIM];
__device__ float g_grad [NATOMS*3];
__device__ float g_e    [NATOMS];
__device__ float g_W0T  [2*HID*DDIM];
__device__ float g_W1T  [2*HID*HID];
__device__ int   g_perm [NATOMS];
__device__ int   g_cnt  [2];

__device__ __forceinline__ float mic(float d){
    return d - BOXF * rintf(d * (1.0f/BOXF));
}
__device__ __forceinline__ float wred(float v){
    v += __shfl_xor_sync(FULLM, v, 16);
    v += __shfl_xor_sync(FULLM, v, 8);
    v += __shfl_xor_sync(FULLM, v, 4);
    v += __shfl_xor_sync(FULLM, v, 2);
    v += __shfl_xor_sync(FULLM, v, 1);
    return v;
}
__device__ __forceinline__ void wmin2(float &d, int &i){
    #pragma unroll
    for (int off = 16; off > 0; off >>= 1){
        float od = __shfl_xor_sync(FULLM, d, off);
        int   oi = __shfl_xor_sync(FULLM, i, off);
        if (od < d){ d = od; i = oi; }
    }
}

// ---------------------------------------------------------------------------
// Prep: weight transposes + grad zero + type-partition permutation (fused)
// ---------------------------------------------------------------------------
__global__ void prep_kernel(const int* __restrict__ types,
    const float* __restrict__ W00, const float* __restrict__ W10,
    const float* __restrict__ W01, const float* __restrict__ W11){
    __shared__ int wb[8][2];
    int tid = threadIdx.x;
    int idx = blockIdx.x*blockDim.x + tid;
    if (idx < 2*DDIM*HID){
        int t = idx / (DDIM*HID);
        int r = idx % (DDIM*HID);
        int d = r / HID, s = r % HID;
        const float* W = t ? W10 : W00;
        g_W0T[t*HID*DDIM + s*DDIM + d] = W[r];
    }
    if (idx < 2*HID*HID){
        int t = idx / (HID*HID);
        int r = idx % (HID*HID);
        int c = r / HID, s = r % HID;
        const float* W = t ? W11 : W01;
        g_W1T[t*HID*HID + s*HID + c] = W[r];
    }
    if (idx < NATOMS*3) g_grad[idx] = 0.0f;
    if (idx < NATOMS){
        int lane = tid & 31, w = tid >> 5;
        unsigned lanelt = (1u << lane) - 1u;
        int t = types[idx];
        unsigned m0 = __ballot_sync(FULLM, t == 0);
        int n0 = __popc(m0);
        if (lane == 0){
            wb[w][0] = atomicAdd(&g_cnt[0], n0);
            wb[w][1] = atomicAdd(&g_cnt[1], 32 - n0);
        }
        __syncwarp();
        int pos = (t == 0) ? (wb[w][0] + __popc(m0 & lanelt))
                           : (NATOMS - 1 - (wb[w][1] + __popc(~m0 & lanelt)));
        g_perm[pos] = idx;
    }
}

// ---------------------------------------------------------------------------
// K1: fused warp-per-atom kNN (d^2 histogram select) + descriptor + frame
// ---------------------------------------------------------------------------
__global__ void knnd_kernel(const float* __restrict__ xyz, const int* __restrict__ types){
    __shared__ float4 sp[NA];
    __shared__ unsigned int hist[WPB][NBINW];
    __shared__ unsigned long long c0buf[WPB][CAPW0];
    __shared__ unsigned long long c1buf[WPB][CAPW1];

    int tid = threadIdx.x;
    int w = tid >> 5, lane = tid & 31;
    int atom = blockIdx.x*WPB + w;
    int b = atom >> 11, i = atom & (NA-1);
    const float* xb = xyz + (size_t)b*NA*3;
    const int* tb = types + (size_t)b*NA;

    for (int j = tid; j < NA; j += WPB*32)
        sp[j] = make_float4(xb[3*j+0], xb[3*j+1], xb[3*j+2], __int_as_float(tb[j]));
    __syncthreads();

    float4 pi = sp[i];
    float xi = pi.x, yi = pi.y, zi = pi.z;

    #pragma unroll
    for (int q = 0; q < NBINW/32; q++) hist[w][lane + 32*q] = 0;
    __syncwarp();

    /* pass 1: packed histogram over d^2 bins (no sqrt) */
    for (int j = lane; j < NA; j += 32){
        if (j == i) continue;
        float4 p = sp[j];
        float dx = mic(xi - p.x + EPSF);
        float dy = mic(yi - p.y + EPSF);
        float dz = mic(zi - p.z + EPSF);
        float d2 = dx*dx + dy*dy + dz*dz;
        int bn = (int)(d2 * BSCALE2); if (bn > NBINW-1) bn = NBINW-1;
        atomicAdd(&hist[w][bn], __float_as_int(p.w) ? 0x10000u : 1u);
    }
    __syncwarp();

    /* threshold scan */
    unsigned chunk = 0;
    #pragma unroll
    for (int q = 0; q < 4; q++) chunk += hist[w][4*lane + q];
    unsigned incl = chunk;
    #pragma unroll
    for (int off = 1; off < 32; off <<= 1){
        unsigned v = __shfl_up_sync(FULLM, incl, off);
        if (lane >= off) incl += v;
    }
    unsigned excl = incl - chunk;

    int thr0, thr1;
    {
        unsigned m0 = __ballot_sync(FULLM, (incl & 0xFFFFu) >= SEL0);
        int fl = __ffs(m0) - 1;
        int tl = 0;
        if (lane == fl){
            int c = (int)(excl & 0xFFFFu);
            int bq = 4*lane;
            #pragma unroll
            for (int q = 0; q < 4; q++){
                c += (int)(hist[w][bq] & 0xFFFFu);
                if (c >= SEL0) break;
                bq++;
            }
            tl = bq;
        }
        thr0 = __shfl_sync(FULLM, tl, fl);
    }
    {
        unsigned m1 = __ballot_sync(FULLM, (incl >> 16) >= SEL1);
        int fl = __ffs(m1) - 1;
        int tl = 0;
        if (lane == fl){
            int c = (int)(excl >> 16);
            int bq = 4*lane;
            #pragma unroll
            for (int q = 0; q < 4; q++){
                c += (int)(hist[w][bq] >> 16);
                if (c >= SEL1) break;
                bq++;
            }
            tl = bq;
        }
        thr1 = __shfl_sync(FULLM, tl, fl);
    }

    /* pass 2: ballot compaction; sqrt only for selected candidates */
    unsigned lanelt = (1u << lane) - 1u;
    int cnt0 = 0, cnt1 = 0;
    for (int j = lane; j < NA; j += 32){
        float4 p = sp[j];
        int t = (j == i) ? 2 : __float_as_int(p.w);
        float dx = mic(xi - p.x + EPSF);
        float dy = mic(yi - p.y + EPSF);
        float dz = mic(zi - p.z + EPSF);
        float d2 = dx*dx + dy*dy + dz*dz;
        int bn = (int)(d2 * BSCALE2); if (bn > NBINW-1) bn = NBINW-1;
        bool p0 = (t == 0) && (bn <= thr0);
        bool p1 = (t == 1) && (bn <= thr1);
        unsigned m0 = __ballot_sync(FULLM, p0);
        unsigned m1 = __ballot_sync(FULLM, p1);
        if (p0 || p1){
            float d = sqrtf(d2);
            unsigned long long key = ((unsigned long long)__float_as_uint(d) << 11)
                                   | (unsigned long long)j;
            if (p0){ int pos = cnt0 + __popc(m0 & lanelt); if (pos < CAPW0) c0buf[w][pos] = key; }
            if (p1){ int pos = cnt1 + __popc(m1 & lanelt); if (pos < CAPW1) c1buf[w][pos] = key; }
        }
        cnt0 += __popc(m0); cnt1 += __popc(m1);
    }
    if (cnt0 > CAPW0) cnt0 = CAPW0;
    if (cnt1 > CAPW1) cnt1 = CAPW1;
    __syncwarp();

    /* rank sort + write; capture top-2 per type via shuffle-argmin */
    float t0d0 = INFINITY, t0d1 = INFINITY; int t0i0 = 0, t0i1 = 0;
    float t1d0 = INFINITY, t1d1 = INFINITY; int t1i0 = 0, t1i1 = 0;

    for (int m = lane; m < cnt0; m += 32){
        unsigned long long k64 = c0buf[w][m];
        int r = 0;
        for (int q = 0; q < cnt0; q++) r += (c0buf[w][q] < k64);
        float dv = __uint_as_float((unsigned)(k64 >> 11));
        int jv = (int)(k64 & 2047ULL);
        if (r == 0){ t0d0 = dv; t0i0 = jv; }
        else if (r == 1){ t0d1 = dv; t0i1 = jv; }
        if (r < SEL0){
            g_dist0[(size_t)atom*SEL0 + r] = dv;
            g_idx0 [(size_t)atom*SEL0 + r] = jv;
        }
    }
    for (int m = lane; m < cnt1; m += 32){
        unsigned long long k64 = c1buf[w][m];
        int r = 0;
        for (int q = 0; q < cnt1; q++) r += (c1buf[w][q] < k64);
        float dv = __uint_as_float((unsigned)(k64 >> 11));
        int jv = (int)(k64 & 2047ULL);
        if (r == 0){ t1d0 = dv; t1i0 = jv; }
        else if (r == 1){ t1d1 = dv; t1i1 = jv; }
        if (r < SEL1){
            g_dist1[(size_t)atom*SEL1 + r] = dv;
            g_idx1 [(size_t)atom*SEL1 + r] = jv;
        }
    }
    __threadfence_block();
    __syncwarp();

    wmin2(t0d0, t0i0); wmin2(t0d1, t0i1);
    wmin2(t1d0, t1i0); wmin2(t1d1, t1i1);

    /* ---- local frame (uniform across warp) ---- */
    float d0, d1; int j0, j1;
    if (t1d0 < t0d0){ d0 = t1d0; j0 = t1i0; } else { d0 = t0d0; j0 = t0i0; }
    if (t1d1 < t0d1){ d1 = t1d1; j1 = t1i1; } else { d1 = t0d1; j1 = t0i1; }

    float4 pj0 = sp[j0], pj1 = sp[j1];
    float rv0x = mic(xi - pj0.x + EPSF);
    float rv0y = mic(yi - pj0.y + EPSF);
    float rv0z = mic(zi - pj0.z + EPSF);
    float rv1x = mic(xi - pj1.x + EPSF);
    float rv1y = mic(yi - pj1.y + EPSF);
    float rv1z = mic(zi - pj1.z + EPSF);

    float inv0 = 1.0f/(d0 + EPSF);
    float inv1 = 1.0f/(d1 + EPSF);
    float r0x = rv0x*inv0, r0y = rv0y*inv0, r0z = rv0z*inv0;
    float r1x = rv1x*inv1, r1y = rv1y*inv1, r1z = rv1z*inv1;

    float s = r0x*r1x + r0y*r1y + r0z*r1z;
    float px = r1x - s*r0x, py = r1y - s*r0y, pz = r1z - s*r0z;
    float np = sqrtf(px*px + py*py + pz*pz);
    float invnp = 1.0f/np;
    float v2x = px*invnp, v2y = py*invnp, v2z = pz*invnp;

    float cx = r0y*r1z - r0z*r1y;
    float cy = r0z*r1x - r0x*r1z;
    float cz = r0x*r1y - r0y*r1x;
    float nc = sqrtf(cx*cx + cy*cy + cz*cz);
    float invnc = 1.0f/nc;
    float v3x = cx*invnc, v3y = cy*invnc, v3z = cz*invnc;

    if (lane == 0){
        g_frame[(size_t)atom*3 + 0] = make_float4(rv0x, rv0y, rv0z, d0);
        g_frame[(size_t)atom*3 + 1] = make_float4(rv1x, rv1y, rv1z, d1);
        g_frame[(size_t)atom*3 + 2] = make_float4(np, nc,
                                     __int_as_float(j0), __int_as_float(j1));
    }

    /* ---- descriptor ---- */
    float* dsc = g_desc + (size_t)atom*DDIM;
    for (int m = lane; m < NRAD; m += 32){
        float sd = (m < SEL0) ? g_dist0[(size_t)atom*SEL0 + m]
                              : g_dist1[(size_t)atom*SEL1 + (m - SEL0)];
        dsc[m] = 1.0f/(sd + EPSF);
    }
    for (int k = lane; k < NANG; k += 32){
        int j; float d;
        if (k < ASEL0){ j = g_idx0[(size_t)atom*SEL0 + k]; d = g_dist0[(size_t)atom*SEL0 + k]; }
        else          { j = g_idx1[(size_t)atom*SEL1 + (k-ASEL0)]; d = g_dist1[(size_t)atom*SEL1 + (k-ASEL0)]; }
        float4 p = sp[j];
        float rx = mic(xi - p.x + EPSF);
        float ry = mic(yi - p.y + EPSF);
        float rz = mic(zi - p.z + EPSF);
        float inv = 1.0f/(d + EPSF);
        float ww = inv*inv;
        dsc[NRAD + 3*k + 0] = (r0x*rx + r0y*ry + r0z*rz)*ww;
        dsc[NRAD + 3*k + 1] = (v2x*rx + v2y*ry + v2z*rz)*ww;
        dsc[NRAD + 3*k + 2] = (v3x*rx + v3y*ry + v3z*rz)*ww;
    }
}

// ---------------------------------------------------------------------------
// K3: fused MLP fwd+bwd, 16 atoms (8 same-type pairs) + K-split, block = 1024
// ---------------------------------------------------------------------------
#define APB 16

__global__ void mlp_kernel(const int* __restrict__ types,
    const float* __restrict__ W00, const float* __restrict__ b00,
    const float* __restrict__ W01, const float* __restrict__ b01,
    const float* __restrict__ W02, const float* __restrict__ b02,
    const float* __restrict__ W10, const float* __restrict__ b10,
    const float* __restrict__ W11, const float* __restrict__ b11,
    const float* __restrict__ W12, const float* __restrict__ b12){

    __shared__ int   satom[APB];
    __shared__ float sX[APB][DDIM];
    __shared__ float ps[2][APB][HID];
    __shared__ float sH1[APB][HID];
    __shared__ float sG[APB][HID];
    __shared__ float sZ[APB][HID];
    __shared__ float red[APB][HID];

    int tid = threadIdx.x;               /* 0..1023 */
    int j = tid & (HID-1);
    int g = (tid >> 6) & 7;              /* pair group 0..7 */
    int half = tid >> 9;                 /* 0 or 1 */
    int base = blockIdx.x * APB;

    if (tid < APB) satom[tid] = g_perm[base + tid];
    __syncthreads();

    for (int d = tid; d < APB*DDIM; d += 1024){
        int aa = d / DDIM, dd = d % DDIM;
        sX[aa][dd] = g_desc[(size_t)satom[aa]*DDIM + dd];
    }
    __syncthreads();

    int a0 = 2*g, a1 = 2*g+1;
    int atom0 = satom[a0], atom1 = satom[a1];
    int t0 = types[atom0], t1 = types[atom1];
    const float* x0 = sX[a0];
    const float* x1 = sX[a1];

    /* ---- layer 1: K split [0,142) / [142,282) ---- */
    int dlo = half ? 142 : 0;
    int dhi = half ? DDIM : 142;
    float p0, p1;
    if (t0 == t1){
        const float* W = t0 ? W10 : W00;
        float e0 = 0.f, e1 = 0.f, o0 = 0.f, o1 = 0.f;
        #pragma unroll 4
        for (int d = dlo; d < dhi; d += 2){
            float w0 = W[d*HID + j];
            float w1 = W[(d+1)*HID + j];
            e0 = fmaf(x0[d],   w0, e0);
            e1 = fmaf(x1[d],   w0, e1);
            o0 = fmaf(x0[d+1], w1, o0);
            o1 = fmaf(x1[d+1], w1, o1);
        }
        p0 = e0 + o0; p1 = e1 + o1;
    } else {
        const float* Wa = t0 ? W10 : W00;
        const float* Wb = t1 ? W10 : W00;
        float e0 = 0.f, e1 = 0.f, o0 = 0.f, o1 = 0.f;
        #pragma unroll 2
        for (int d = dlo; d < dhi; d += 2){
            e0 = fmaf(x0[d],   Wa[d*HID + j],     e0);
            e1 = fmaf(x1[d],   Wb[d*HID + j],     e1);
            o0 = fmaf(x0[d+1], Wa[(d+1)*HID + j], o0);
            o1 = fmaf(x1[d+1], Wb[(d+1)*HID + j], o1);
        }
        p0 = e0 + o0; p1 = e1 + o1;
    }
    ps[half][a0][j] = p0;
    ps[half][a1][j] = p1;
    __syncthreads();

    float h1a = 0.f, h1b = 0.f;
    if (half == 0){
        h1a = tanhf(ps[0][a0][j] + ps[1][a0][j] + (t0 ? b10 : b00)[j]);
        h1b = tanhf(ps[0][a1][j] + ps[1][a1][j] + (t1 ? b10 : b00)[j]);
        sH1[a0][j] = h1a;
        sH1[a1][j] = h1b;
    }
    __syncthreads();

    /* ---- layer 2: K split 32/32 ---- */
    int slo = half*32;
    const float* h0 = sH1[a0];
    const float* h1r = sH1[a1];
    float q0 = 0.f, q1 = 0.f;
    if (t0 == t1){
        const float* W = t0 ? W11 : W01;
        #pragma unroll 8
        for (int q = 0; q < 32; q++){
            int ss = slo + q;
            float w = W[ss*HID + j];
            q0 = fmaf(h0[ss],  w, q0);
            q1 = fmaf(h1r[ss], w, q1);
        }
    } else {
        const float* Wa = t0 ? W11 : W01;
        const float* Wb = t1 ? W11 : W01;
        #pragma unroll 8
        for (int q = 0; q < 32; q++){
            int ss = slo + q;
            q0 = fmaf(h0[ss],  Wa[ss*HID + j], q0);
            q1 = fmaf(h1r[ss], Wb[ss*HID + j], q1);
        }
    }
    ps[half][a0][j] = q0;
    ps[half][a1][j] = q1;
    __syncthreads();

    if (half == 0){
        float h2a = tanhf(ps[0][a0][j] + ps[1][a0][j] + (t0 ? b11 : b01)[j]);
        float h2b = tanhf(ps[0][a1][j] + ps[1][a1][j] + (t1 ? b11 : b01)[j]);
        float w2a = (t0 ? W12 : W02)[j];
        float w2b = (t1 ? W12 : W02)[j];
        red[a0][j] = h2a * w2a;
        red[a1][j] = h2b * w2b;
        sG[a0][j] = w2a * (1.0f - h2a*h2a);
        sG[a1][j] = w2b * (1.0f - h2b*h2b);
    }
    __syncthreads();

    /* energy reduce on first 16 warps */
    if (half == 0){
        int ww = tid >> 5, lane = tid & 31;
        float v = red[ww][lane] + red[ww][lane+32];
        v = wred(v);
        if (lane == 0){
            int at = satom[ww];
            int tt = types[at];
            g_e[at] = v + (tt ? b12 : b02)[0];
        }
    }

    /* ---- bwd1: K split 32/32 ---- */
    const float* ga = sG[a0];
    const float* gb = sG[a1];
    float r0 = 0.f, r1 = 0.f;
    if (t0 == t1){
        const float* WT = g_W1T + (size_t)t0*HID*HID;
        #pragma unroll 8
        for (int q = 0; q < 32; q++){
            int ss = slo + q;
            float w = WT[ss*HID + j];
            r0 = fmaf(ga[ss], w, r0);
            r1 = fmaf(gb[ss], w, r1);
        }
    } else {
        const float* WTa = g_W1T + (size_t)t0*HID*HID;
        const float* WTb = g_W1T + (size_t)t1*HID*HID;
        #pragma unroll 8
        for (int q = 0; q < 32; q++){
            int ss = slo + q;
            r0 = fmaf(ga[ss], WTa[ss*HID + j], r0);
            r1 = fmaf(gb[ss], WTb[ss*HID + j], r1);
        }
    }
    ps[half][a0][j] = r0;
    ps[half][a1][j] = r1;
    __syncthreads();

    if (half == 0){
        sZ[a0][j] = (ps[0][a0][j] + ps[1][a0][j]) * (1.0f - h1a*h1a);
        sZ[a1][j] = (ps[0][a1][j] + ps[1][a1][j]) * (1.0f - h1b*h1b);
    }
    __syncthreads();

    /* ---- bwd2: d strided by 128 over both halves ---- */
    const float* z0 = sZ[a0];
    const float* z1 = sZ[a1];
    if (t0 == t1){
        const float* WT = g_W0T + (size_t)t0*HID*DDIM;
        for (int d = j + 64*half; d < DDIM; d += 128){
            float u0 = 0.f, u1 = 0.f;
            #pragma unroll 8
            for (int ss = 0; ss < HID; ss++){
                float w = WT[ss*DDIM + d];
                u0 = fmaf(z0[ss], w, u0);
                u1 = fmaf(z1[ss], w, u1);
            }
            g_gdesc[(size_t)atom0*DDIM + d] = u0;
            g_gdesc[(size_t)atom1*DDIM + d] = u1;
        }
    } else {
        const float* WTa = g_W0T + (size_t)t0*HID*DDIM;
        const float* WTb = g_W0T + (size_t)t1*HID*DDIM;
        for (int d = j + 64*half; d < DDIM; d += 128){
            float u0 = 0.f, u1 = 0.f;
            #pragma unroll 8
            for (int ss = 0; ss < HID; ss++){
                u0 = fmaf(z0[ss], WTa[ss*DDIM + d], u0);
                u1 = fmaf(z1[ss], WTb[ss*DDIM + d], u1);
            }
            g_gdesc[(size_t)atom0*DDIM + d] = u0;
            g_gdesc[(size_t)atom1*DDIM + d] = u1;
        }
    }
}

// ---------------------------------------------------------------------------
// K4: descriptor backward — single merged loop, one atomic triple per neighbor
// ---------------------------------------------------------------------------
__global__ void __launch_bounds__(512, 2)
bwd_kernel(const float* __restrict__ xyz){
    __shared__ float4 sp[NA];
    int tid = threadIdx.x;
    int w = tid >> 5, lane = tid & 31;
    int atom = blockIdx.x*BWPB + w;
    int b = atom >> 11, i = atom & (NA-1);
    const float* xb = xyz + (size_t)b*NA*3;

    for (int j = tid; j < NA; j += BWPB*32)
        sp[j] = make_float4(xb[3*j+0], xb[3*j+1], xb[3*j+2], 0.0f);
    __syncthreads();

    float4 pi = sp[i];
    float xi = pi.x, yi = pi.y, zi = pi.z;

    /* cached frame */
    float4 f0 = g_frame[(size_t)atom*3 + 0];
    float4 f1 = g_frame[(size_t)atom*3 + 1];
    float4 f2 = g_frame[(size_t)atom*3 + 2];
    float rv0x = f0.x, rv0y = f0.y, rv0z = f0.z, d0 = f0.w;
    float rv1x = f1.x, rv1y = f1.y, rv1z = f1.z, d1 = f1.w;
    float np = f2.x, nc = f2.y;
    int j0 = __float_as_int(f2.z), j1 = __float_as_int(f2.w);

    float inv0 = 1.0f/(d0 + EPSF);
    float inv1 = 1.0f/(d1 + EPSF);
    float r0x = rv0x*inv0, r0y = rv0y*inv0, r0z = rv0z*inv0;
    float r1x = rv1x*inv1, r1y = rv1y*inv1, r1z = rv1z*inv1;

    float s = r0x*r1x + r0y*r1y + r0z*r1z;
    float px = r1x - s*r0x, py = r1y - s*r0y, pz = r1z - s*r0z;
    float invnp = 1.0f/np;
    float v2x = px*invnp, v2y = py*invnp, v2z = pz*invnp;

    float cx = r0y*r1z - r0z*r1y;
    float cy = r0z*r1x - r0x*r1z;
    float cz = r0x*r1y - r0y*r1x;
    float invnc = 1.0f/nc;
    float v3x = cx*invnc, v3y = cy*invnc, v3z = cz*invnc;

    const float* gd = g_gdesc + (size_t)atom*DDIM;
    float* gradb = g_grad + (size_t)b*NA*3;

    float G0=0,G1=0,G2=0,G3=0,G4=0,G5=0,G6=0,G7=0,G8=0;
    float gix=0, giy=0, giz=0;

    for (int m = lane; m < NRAD; m += 32){
        int j; float sd; int k;
        if (m < SEL0){
            j = g_idx0[(size_t)atom*SEL0 + m];
            sd = g_dist0[(size_t)atom*SEL0 + m];
            k = (m < ASEL0) ? m : -1;
        } else {
            int mm = m - SEL0;
            j = g_idx1[(size_t)atom*SEL1 + mm];
            sd = g_dist1[(size_t)atom*SEL1 + mm];
            k = (mm < ASEL1) ? (ASEL0 + mm) : -1;
        }
        float4 p = sp[j];
        float rx = mic(xi - p.x + EPSF);
        float ry = mic(yi - p.y + EPSF);
        float rz = mic(zi - p.z + EPSF);
        float invr = 1.0f/(sd + EPSF);

        float gR = gd[m];
        float cfr = -gR*invr*invr / sd;
        float gtx = cfr*rx, gty = cfr*ry, gtz = cfr*rz;

        if (k >= 0){
            float gx = gd[NRAD + 3*k + 0];
            float gy = gd[NRAD + 3*k + 1];
            float gz3= gd[NRAD + 3*k + 2];
            float ww = invr*invr;
            float Arx = r0x*rx + r0y*ry + r0z*rz;
            float Ary = v2x*rx + v2y*ry + v2z*rz;
            float Arz = v3x*rx + v3y*ry + v3z*rz;
            float gvx = (r0x*gx + v2x*gy + v3x*gz3)*ww;
            float gvy = (r0y*gx + v2y*gy + v3y*gz3)*ww;
            float gvz = (r0z*gx + v2z*gy + v3z*gz3)*ww;
            float gdd = (gx*Arx + gy*Ary + gz3*Arz) * (-2.0f*ww*invr);
            G0 += ww*gx*rx;  G1 += ww*gx*ry;  G2 += ww*gx*rz;
            G3 += ww*gy*rx;  G4 += ww*gy*ry;  G5 += ww*gy*rz;
            G6 += ww*gz3*rx; G7 += ww*gz3*ry; G8 += ww*gz3*rz;
            float cfa = gdd / sd;
            gtx += gvx + cfa*rx;
            gty += gvy + cfa*ry;
            gtz += gvz + cfa*rz;
        }

        gix += gtx; giy += gty; giz += gtz;
        atomicAdd(&gradb[3*j+0], -gtx);
        atomicAdd(&gradb[3*j+1], -gty);
        atomicAdd(&gradb[3*j+2], -gtz);
    }

    G0 = wred(G0); G1 = wred(G1); G2 = wred(G2);
    G3 = wred(G3); G4 = wred(G4); G5 = wred(G5);
    G6 = wred(G6); G7 = wred(G7); G8 = wred(G8);
    gix = wred(gix); giy = wred(giy); giz = wred(giz);

    if (lane == 0){
        float dr0x = G0, dr0y = G1, dr0z = G2;
        float dr1x = 0.f, dr1y = 0.f, dr1z = 0.f;

        float t1v = G3*v2x + G4*v2y + G5*v2z;
        float gpx = (G3 - t1v*v2x)*invnp;
        float gpy = (G4 - t1v*v2y)*invnp;
        float gpz = (G5 - t1v*v2z)*invnp;
        float gpr0 = gpx*r0x + gpy*r0y + gpz*r0z;
        dr1x += gpx - gpr0*r0x;
        dr1y += gpy - gpr0*r0y;
        dr1z += gpz - gpr0*r0z;
        dr0x += -s*gpx - gpr0*r1x;
        dr0y += -s*gpy - gpr0*r1y;
        dr0z += -s*gpz - gpr0*r1z;

        float t2v = G6*v3x + G7*v3y + G8*v3z;
        float gcx = (G6 - t2v*v3x)*invnc;
        float gcy = (G7 - t2v*v3y)*invnc;
        float gcz = (G8 - t2v*v3z)*invnc;
        dr0x += r1y*gcz - r1z*gcy;
        dr0y += r1z*gcx - r1x*gcz;
        dr0z += r1x*gcy - r1y*gcx;
        dr1x += gcy*r0z - gcz*r0y;
        dr1y += gcz*r0x - gcx*r0z;
        dr1z += gcx*r0y - gcy*r0x;

        float dd0 = (dr0x*rv0x + dr0y*rv0y + dr0z*rv0z) * (-inv0*inv0);
        float c0 = dd0 / d0;
        float gt0x = dr0x*inv0 + c0*rv0x;
        float gt0y = dr0y*inv0 + c0*rv0y;
        float gt0z = dr0z*inv0 + c0*rv0z;
        atomicAdd(&gradb[3*j0+0], -gt0x);
        atomicAdd(&gradb[3*j0+1], -gt0y);
        atomicAdd(&gradb[3*j0+2], -gt0z);

        float dd1 = (dr1x*rv1x + dr1y*rv1y + dr1z*rv1z) * (-inv1*inv1);
        float c1 = dd1 / d1;
        float gt1x = dr1x*inv1 + c1*rv1x;
        float gt1y = dr1y*inv1 + c1*rv1y;
        float gt1z = dr1z*inv1 + c1*rv1z;
        atomicAdd(&gradb[3*j1+0], -gt1x);
        atomicAdd(&gradb[3*j1+1], -gt1y);
        atomicAdd(&gradb[3*j1+2], -gt1z);

        atomicAdd(&gradb[3*i+0], gix + gt0x + gt1x);
        atomicAdd(&gradb[3*i+1], giy + gt0y + gt1y);
        atomicAdd(&gradb[3*i+2], giz + gt0z + gt1z);
    }
}

// ---------------------------------------------------------------------------
// Output
// ---------------------------------------------------------------------------
__global__ void out_kernel(float* __restrict__ out){
    if (blockIdx.x < 48){
        int idx = blockIdx.x*256 + threadIdx.x;
        if (idx < NATOMS*3) out[2 + idx] = -g_grad[idx];
    } else {
        __shared__ float red[256];
        int b = blockIdx.x - 48;
        int tid = threadIdx.x;
        float acc = 0.0f;
        for (int i2 = tid; i2 < NA; i2 += 256) acc += g_e[b*NA + i2];
        red[tid] = acc;
        __syncthreads();
        for (int off = 128; off > 0; off >>= 1){
            if (tid < off) red[tid] += red[tid + off];
            __syncthreads();
        }
        if (tid == 0) out[b] = red[0];
    }
}

// ---------------------------------------------------------------------------
extern "C" void kernel_launch(void* const* d_in, const int* in_sizes, int n_in,
                              void* d_out, int out_size){
    const float* xyz   = (const float*)d_in[0];
    const int*   types = (const int*)  d_in[1];
    const float* W00=(const float*)d_in[3],  *b00=(const float*)d_in[4];
    const float* W01=(const float*)d_in[5],  *b01=(const float*)d_in[6];
    const float* W02=(const float*)d_in[7],  *b02=(const float*)d_in[8];
    const float* W10=(const float*)d_in[9],  *b10=(const float*)d_in[10];
    const float* W11=(const float*)d_in[11], *b11=(const float*)d_in[12];
    const float* W12=(const float*)d_in[13], *b12=(const float*)d_in[14];
    float* out = (float*)d_out;

    void* cptr = 0;
    cudaGetSymbolAddress(&cptr, g_cnt);
    cudaMemsetAsync(cptr, 0, 2*sizeof(int));

    prep_kernel<<<(2*DDIM*HID + 255)/256, 256>>>(types, W00, W10, W01, W11); /* 1 */
    knnd_kernel<<<NATOMS/WPB, WPB*32>>>(xyz, types);                         /* 2 */
    mlp_kernel<<<NATOMS/APB, 1024>>>(types, W00,b00,W01,b01,W02,b02,         /* 3 */
                                            W10,b10,W11,b11,W12,b12);
    bwd_kernel<<<NATOMS/BWPB, BWPB*32>>>(xyz);                               /* 4: profiled */
    out_kernel<<<50, 256>>>(out);                                            /* 5 */
}